// round 10
// baseline (speedup 1.0000x reference)
#include <cuda_runtime.h>
#include <cstdint>

#define H  128
#define NH 8
#define NQ 2304

// Transposed Wq/Wv/Wrv/Wo: slot = ((s*4+m)*2+l), m: 0=Wq 1=Wv 2=Wrv 3=Wo
__device__ float g_WT[24 * H * H];
__device__ float g_u [NQ * 1024];
__device__ float g_w [NQ * 1024];
__device__ float g_vb[NQ * 1024];   // [q>>2][n*128+i][q&3]
__device__ float g_rb[NQ * 1024];
__device__ float g_buf0[NQ * H];
__device__ float g_buf1[NQ * H];

__global__ void transpose_w(const float* p0, const float* p1, const float* p2,
                            const float* p3, const float* p4, const float* p5,
                            const float* p6, const float* p7, const float* p8,
                            const float* p9, const float* p10, const float* p11)
{
    const float* ps[12] = {p0,p1,p2,p3,p4,p5,p6,p7,p8,p9,p10,p11};
    int slot = blockIdx.x >> 2;                  // 0..23
    int part = blockIdx.x & 3;
    int sm = slot >> 1, l = slot & 1;
    const float* Wm = ps[sm] + l * H * H;
    float* O = g_WT + slot * H * H;
    int t = threadIdx.x;
    for (int c = part * 32; c < part * 32 + 32; ++c)
        O[c * H + t] = Wm[t * H + c];
}

__device__ __forceinline__ void cp16(uint32_t dst, const float* src) {
    asm volatile("cp.async.cg.shared.global [%0], [%1], 16;" :: "r"(dst), "l"(src));
}

__device__ __forceinline__ float dot4(float4 a, float4 b) {
    return a.x * b.x + a.y * b.y + a.z * b.z + a.w * b.w;
}

// ---- u/w head projection from qh in smem; Wk/Wrk in ORIGINAL layout ----------
__device__ __forceinline__ void uw_heads(
    const float (*sqh)[128], int g, int t, int q0,
    const float* __restrict__ Wk, const float* __restrict__ Wrk,
    float* __restrict__ gu, float* __restrict__ gw)
{
    #pragma unroll 1
    for (int nn = 0; nn < 4; ++nn) {
        int n = 4 * g + nn;
        float4 wk0 = *(const float4*)&Wk [t * H + n * 16     ];
        float4 wk1 = *(const float4*)&Wk [t * H + n * 16 + 4 ];
        float4 wk2 = *(const float4*)&Wk [t * H + n * 16 + 8 ];
        float4 wk3 = *(const float4*)&Wk [t * H + n * 16 + 12];
        float4 wr0 = *(const float4*)&Wrk[t * H + n * 16     ];
        float4 wr1 = *(const float4*)&Wrk[t * H + n * 16 + 4 ];
        float4 wr2 = *(const float4*)&Wrk[t * H + n * 16 + 8 ];
        float4 wr3 = *(const float4*)&Wrk[t * H + n * 16 + 12];
        #pragma unroll
        for (int q = 0; q < 4; ++q) {
            float4 qa = *(const float4*)&sqh[q][n * 16     ];
            float4 qb = *(const float4*)&sqh[q][n * 16 + 4 ];
            float4 qc = *(const float4*)&sqh[q][n * 16 + 8 ];
            float4 qd = *(const float4*)&sqh[q][n * 16 + 12];
            float u = dot4(qa, wk0) + dot4(qb, wk1) + dot4(qc, wk2) + dot4(qd, wk3);
            float w = dot4(qa, wr0) + dot4(qb, wr1) + dot4(qc, wr2) + dot4(qd, wr3);
            gu[(q0 + q) * 1024 + n * H + t] = u;
            gw[(q0 + q) * 1024 + n * H + t] = w;
        }
    }
}

// ---------------- Kernel A (first stage only) ---------------------------------
__global__ __launch_bounds__(256) void stage_uw(
    const float* __restrict__ xin,
    const float* __restrict__ WqT,
    const float* __restrict__ Wk, const float* __restrict__ Wrk,
    float* __restrict__ gu, float* __restrict__ gw)
{
    __shared__ float sx [4][128];
    __shared__ float sqh[4][128];
    const int tid = threadIdx.x;
    const int t = tid & 127, g = tid >> 7;
    const int q0 = blockIdx.x * 4;

    for (int e = tid; e < 512; e += 256)
        sx[e >> 7][e & 127] = xin[q0 * H + e];
    __syncthreads();

    {
        float a0 = 0.f, a1 = 0.f;
        #pragma unroll 8
        for (int i = 0; i < H; i += 4) {
            float4 wq = *(const float4*)&WqT[t * H + i];
            float4 x0 = *(const float4*)&sx[2 * g][i];
            float4 x1 = *(const float4*)&sx[2 * g + 1][i];
            a0 += dot4(x0, wq);
            a1 += dot4(x1, wq);
        }
        sqh[2 * g    ][t] = a0;
        sqh[2 * g + 1][t] = a1;
    }
    __syncthreads();
    uw_heads(sqh, g, t, q0, Wk, Wrk, gu, gw);
}

// ---------------- Kernel B: weight-free attention core -----------------------
// B: log2 of s-slot width. P = 128>>B parts, i-chunk C = 1<<B.
__global__ __launch_bounds__(128) void attn_core(
    const float* __restrict__ gu, const float* __restrict__ gw,
    const float* __restrict__ ksrc, const float* __restrict__ rpesrc,
    const int* __restrict__ knn, const unsigned char* __restrict__ mask,
    float* __restrict__ gvb, float* __restrict__ grb,
    int stage, int S, int B)
{
    extern __shared__ float sm[];
    float* sm_u   = sm;              // 1024 [n*128+i]
    float* sm_w   = sm + 1024;       // 1024
    float* sm_scp = sm + 2048;       // P*512 partials; slot p=0 holds probs
    const int P = 128 >> B;
    float* sm_k   = sm_scp + P * 512;  // S*132
    float* sm_r   = sm_k + S * 132;

    __shared__ int kbase[64], rbase[64], mflag[64];

    const int q = blockIdx.x;
    const int t = threadIdx.x;

    if (t < S) {
        int kb, rb, mf;
        if (stage == 1) {
            kb = (q * S + t) * H; rb = kb;
            mf = mask[q * S + t];
        } else if (stage == 2) {
            int idx = knn[q * 32 + t];
            kb = (q * 128 + idx) * H; rb = kb;
            mf = mask[q * 128 + idx];
        } else {
            int g = q / 48, qn = q % 48;
            int idx = knn[(g * 48 + qn) * 16 + t];
            kb = ((g * 48 + idx) * 50 + 49) * H;
            rb = ((g * 48 + qn) * 48 + idx) * H;
            mf = mask[(g * 48 + qn) * 48 + idx];
        }
        kbase[t] = kb; rbase[t] = rb; mflag[t] = mf;
    }
    __syncthreads();

    {
        uint32_t su  = (uint32_t)__cvta_generic_to_shared(sm_u);
        uint32_t sw  = (uint32_t)__cvta_generic_to_shared(sm_w);
        for (int c = t; c < 256; c += 128) {
            cp16(su + c * 16, gu + q * 1024 + c * 4);
            cp16(sw + c * 16, gw + q * 1024 + c * 4);
        }
        uint32_t smk = (uint32_t)__cvta_generic_to_shared(sm_k);
        uint32_t smr = (uint32_t)__cvta_generic_to_shared(sm_r);
        for (int c = t; c < S * 32; c += 128) {
            int s = c >> 5, j = c & 31;
            cp16(smk + s * 528 + j * 16, ksrc   + kbase[s] + j * 4);
            cp16(smr + s * 528 + j * 16, rpesrc + rbase[s] + j * 4);
        }
        asm volatile("cp.async.commit_group;");
        asm volatile("cp.async.wait_group 0;");
    }
    __syncthreads();

    // scores: thread = (part p, key s); part p covers i in [p<<B, (p+1)<<B).
    {
        int p = t >> B, s = t & ((1 << B) - 1);
        if (s < S) {
            int i0 = p << B;
            const int C = 1 << B;
            const float* kk = &sm_k[s * 132 + i0];
            const float* rr = &sm_r[s * 132 + i0];
            float acc[NH];
            #pragma unroll
            for (int n = 0; n < NH; ++n) acc[n] = 0.f;
            #pragma unroll 4
            for (int ii = 0; ii < C; ii += 4) {
                float4 k4 = *(const float4*)(kk + ii);
                float4 r4 = *(const float4*)(rr + ii);
                #pragma unroll
                for (int n = 0; n < NH; ++n) {
                    float4 u4 = *(const float4*)(sm_u + n * 128 + i0 + ii);
                    float4 w4 = *(const float4*)(sm_w + n * 128 + i0 + ii);
                    acc[n] += k4.x * u4.x + k4.y * u4.y + k4.z * u4.z + k4.w * u4.w
                            + r4.x * w4.x + r4.y * w4.y + r4.z * w4.z + r4.w * w4.w;
                }
            }
            #pragma unroll
            for (int n = 0; n < NH; ++n) sm_scp[p * 512 + s * NH + n] = acc[n];
        }
    }
    __syncthreads();

    // softmax: 128 threads, 16 lanes per head (xor 8,4,2,1 stays in-group).
    {
        int n = t >> 4, j = t & 15;
        float mx = -1e30f;
        for (int s = j; s < S; s += 16) {
            float v = 0.f;
            for (int p = 0; p < P; ++p) v += sm_scp[p * 512 + s * NH + n];
            v *= 0.25f;
            if (mflag[s]) v = -1e9f;
            sm_scp[s * NH + n] = v;
            mx = fmaxf(mx, v);
        }
        #pragma unroll
        for (int o = 8; o; o >>= 1) mx = fmaxf(mx, __shfl_xor_sync(0xffffffffu, mx, o));
        float sum = 0.f;
        for (int s = j; s < S; s += 16) {
            float pe = __expf(sm_scp[s * NH + n] - mx);
            sm_scp[s * NH + n] = pe; sum += pe;
        }
        #pragma unroll
        for (int o = 8; o; o >>= 1) sum += __shfl_xor_sync(0xffffffffu, sum, o);
        float inv = 1.f / sum;
        for (int s = j; s < S; s += 16) sm_scp[s * NH + n] *= inv;
    }
    __syncthreads();

    {
        float vb[NH], rb2[NH];
        #pragma unroll
        for (int n = 0; n < NH; ++n) { vb[n] = 0.f; rb2[n] = 0.f; }
        for (int s = 0; s < S; ++s) {
            float kv = sm_k[s * 132 + t];
            float rv = sm_r[s * 132 + t];
            float4 p0 = *(const float4*)&sm_scp[s * NH];
            float4 p1 = *(const float4*)&sm_scp[s * NH + 4];
            vb[0] += p0.x * kv;  rb2[0] += p0.x * rv;
            vb[1] += p0.y * kv;  rb2[1] += p0.y * rv;
            vb[2] += p0.z * kv;  rb2[2] += p0.z * rv;
            vb[3] += p0.w * kv;  rb2[3] += p0.w * rv;
            vb[4] += p1.x * kv;  rb2[4] += p1.x * rv;
            vb[5] += p1.y * kv;  rb2[5] += p1.y * rv;
            vb[6] += p1.z * kv;  rb2[6] += p1.z * rv;
            vb[7] += p1.w * kv;  rb2[7] += p1.w * rv;
        }
        int base = (q & ~3) * 1024 + (q & 3);
        #pragma unroll
        for (int n = 0; n < NH; ++n) {
            gvb[base + (n * 128 + t) * 4] = vb[n];
            grb[base + (n * 128 + t) * 4] = rb2[n];
        }
    }
}

// ---------------- Kernel C+A': out_proj fused with next-stage uw -------------
__global__ __launch_bounds__(256) void out_proj_uw(
    const float* __restrict__ xin,
    const float* __restrict__ gvb, const float* __restrict__ grb,
    const float* __restrict__ WvT, const float* __restrict__ WrvT,
    const float* __restrict__ WoT,
    float* __restrict__ xout,
    const float* __restrict__ WqT2,
    const float* __restrict__ Wk2, const float* __restrict__ Wrk2,
    float* __restrict__ gu, float* __restrict__ gw, int do_next)
{
    __shared__ __align__(16) float svb4[4096];   // [n*128+i][q]
    __shared__ __align__(16) float srb4[4096];
    __shared__ __align__(16) float sof4[512];    // [i][q]
    __shared__ __align__(16) float sxo[4][128];
    __shared__ __align__(16) float part[2][4][128];

    const int tid = threadIdx.x;
    const int t = tid & 127, g = tid >> 7;
    const int q0 = blockIdx.x * 4;
    const int n = t >> 4;
    const int i0 = g * 64;

    {
        uint32_t a = (uint32_t)__cvta_generic_to_shared(svb4);
        uint32_t b = (uint32_t)__cvta_generic_to_shared(srb4);
        for (int c = tid; c < 1024; c += 256) {
            cp16(a + c * 16, gvb + q0 * 1024 + c * 4);
            cp16(b + c * 16, grb + q0 * 1024 + c * 4);
        }
        asm volatile("cp.async.commit_group;");
        asm volatile("cp.async.wait_group 0;");
    }
    __syncthreads();

    // Phase 1: of[q][t] = vb[q][n]·Wv[:,t] + rb[q][n]·Wrv[:,t]
    {
        float a0 = 0.f, a1 = 0.f, a2 = 0.f, a3 = 0.f;
        #pragma unroll 4
        for (int ii = 0; ii < 64; ii += 4) {
            int i = i0 + ii;
            float4 wv = *(const float4*)&WvT [t * H + i];
            float4 wr = *(const float4*)&WrvT[t * H + i];
            float4 v0 = *(const float4*)&svb4[(n * 128 + i    ) * 4];
            float4 r0 = *(const float4*)&srb4[(n * 128 + i    ) * 4];
            a0 += v0.x * wv.x + r0.x * wr.x;  a1 += v0.y * wv.x + r0.y * wr.x;
            a2 += v0.z * wv.x + r0.z * wr.x;  a3 += v0.w * wv.x + r0.w * wr.x;
            float4 v1 = *(const float4*)&svb4[(n * 128 + i + 1) * 4];
            float4 r1 = *(const float4*)&srb4[(n * 128 + i + 1) * 4];
            a0 += v1.x * wv.y + r1.x * wr.y;  a1 += v1.y * wv.y + r1.y * wr.y;
            a2 += v1.z * wv.y + r1.z * wr.y;  a3 += v1.w * wv.y + r1.w * wr.y;
            float4 v2 = *(const float4*)&svb4[(n * 128 + i + 2) * 4];
            float4 r2 = *(const float4*)&srb4[(n * 128 + i + 2) * 4];
            a0 += v2.x * wv.z + r2.x * wr.z;  a1 += v2.y * wv.z + r2.y * wr.z;
            a2 += v2.z * wv.z + r2.z * wr.z;  a3 += v2.w * wv.z + r2.w * wr.z;
            float4 v3 = *(const float4*)&svb4[(n * 128 + i + 3) * 4];
            float4 r3 = *(const float4*)&srb4[(n * 128 + i + 3) * 4];
            a0 += v3.x * wv.w + r3.x * wr.w;  a1 += v3.y * wv.w + r3.y * wr.w;
            a2 += v3.z * wv.w + r3.z * wr.w;  a3 += v3.w * wv.w + r3.w * wr.w;
        }
        part[g][0][t] = a0; part[g][1][t] = a1;
        part[g][2][t] = a2; part[g][3][t] = a3;
    }
    __syncthreads();
    if (g == 0) {
        float4 o;
        o.x = part[0][0][t] + part[1][0][t];
        o.y = part[0][1][t] + part[1][1][t];
        o.z = part[0][2][t] + part[1][2][t];
        o.w = part[0][3][t] + part[1][3][t];
        *(float4*)&sof4[t * 4] = o;
    }
    __syncthreads();

    // Phase 2: x_out = x + of @ Wo
    {
        float a0 = 0.f, a1 = 0.f, a2 = 0.f, a3 = 0.f;
        #pragma unroll 4
        for (int ii = 0; ii < 64; ii += 4) {
            int i = i0 + ii;
            float4 wo = *(const float4*)&WoT[t * H + i];
            float4 f0 = *(const float4*)&sof4[(i    ) * 4];
            float4 f1 = *(const float4*)&sof4[(i + 1) * 4];
            float4 f2 = *(const float4*)&sof4[(i + 2) * 4];
            float4 f3 = *(const float4*)&sof4[(i + 3) * 4];
            a0 += f0.x * wo.x + f1.x * wo.y + f2.x * wo.z + f3.x * wo.w;
            a1 += f0.y * wo.x + f1.y * wo.y + f2.y * wo.z + f3.y * wo.w;
            a2 += f0.z * wo.x + f1.z * wo.y + f2.z * wo.z + f3.z * wo.w;
            a3 += f0.w * wo.x + f1.w * wo.y + f2.w * wo.z + f3.w * wo.w;
        }
        part[g][0][t] = a0; part[g][1][t] = a1;
        part[g][2][t] = a2; part[g][3][t] = a3;
    }
    __syncthreads();
    if (g == 0) {
        #pragma unroll
        for (int q = 0; q < 4; ++q) {
            float v = xin[(q0 + q) * H + t] + part[0][q][t] + part[1][q][t];
            sxo[q][t] = v;
            xout[(q0 + q) * H + t] = v;
        }
    }
    __syncthreads();

    if (!do_next) return;

    // Phase 3: next-stage qh = x_out @ Wq2
    {
        float a0 = 0.f, a1 = 0.f;
        #pragma unroll 8
        for (int i = 0; i < H; i += 4) {
            float4 wq = *(const float4*)&WqT2[t * H + i];
            float4 x0 = *(const float4*)&sxo[2 * g][i];
            float4 x1 = *(const float4*)&sxo[2 * g + 1][i];
            a0 += dot4(x0, wq);
            a1 += dot4(x1, wq);
        }
        part[0][2 * g    ][t] = a0;
        part[0][2 * g + 1][t] = a1;
    }
    __syncthreads();

    // Phase 4: next-stage u/w.
    uw_heads((const float (*)[128])part[0], g, t, q0, Wk2, Wrk2, gu, gw);
}

extern "C" void kernel_launch(void* const* d_in, const int* in_sizes, int n_in,
                              void* d_out, int out_size)
{
    bool sig = (in_sizes[6] == 32768);

    const float* x_m    = (const float*)d_in[0];
    const float* x_a    = (const float*)d_in[1];
    const float* x_pl   = (const float*)d_in[2];
    const float* rpe_t  = (const float*)d_in[3];
    const float* rpe_pl = (const float*)d_in[4];
    const float* rpe_a  = (const float*)d_in[5];

    const float* W[3][6];
    int wb = sig ? 6 : 11;
    for (int s = 0; s < 3; ++s)
        for (int j = 0; j < 6; ++j)
            W[s][j] = (const float*)d_in[wb + s * 6 + j];

    int kb = sig ? 24 : 6;
    const int* knn_pl = (const int*)d_in[kb + 0];
    const int* knn_a  = (const int*)d_in[kb + 1];
    const unsigned char* mk_t  = (const unsigned char*)d_in[kb + 2];
    const unsigned char* mk_pl = (const unsigned char*)d_in[kb + 3];
    const unsigned char* mk_a  = (const unsigned char*)d_in[kb + 4];

    cudaFuncSetAttribute(attn_core, cudaFuncAttributeMaxDynamicSharedMemorySize, 65088);

    float *buf0, *buf1, *wt, *gu, *gw, *gvb, *grb;
    cudaGetSymbolAddress((void**)&buf0, g_buf0);
    cudaGetSymbolAddress((void**)&buf1, g_buf1);
    cudaGetSymbolAddress((void**)&wt,   g_WT);
    cudaGetSymbolAddress((void**)&gu,   g_u);
    cudaGetSymbolAddress((void**)&gw,   g_w);
    cudaGetSymbolAddress((void**)&gvb,  g_vb);
    cudaGetSymbolAddress((void**)&grb,  g_rb);

    // Transpose Wq, Wv, Wrv, Wo for all stages (both layers).
    transpose_w<<<96, 128>>>(W[0][0], W[0][2], W[0][4], W[0][5],
                             W[1][0], W[1][2], W[1][4], W[1][5],
                             W[2][0], W[2][2], W[2][4], W[2][5]);

    // WT slot helper: ((s*4+m)*2+l)*H*H, m: 0=Wq 1=Wv 2=Wrv 3=Wo
    #define WT(s, m, l) (wt + (((s) * 4 + (m)) * 2 + (l)) * H * H)

    const int Ss[3] = {50, 32, 16};
    const int Bs[3] = {6, 5, 4};
    const float* cur = x_m;
    float* bufs[2] = {buf0, buf1};
    int bi = 0;

    // First-stage u/w.
    stage_uw<<<NQ / 4, 256>>>(x_m, WT(0, 0, 0), W[0][1], W[0][3], gu, gw);

    for (int idx = 0; idx < 6; ++idx) {
        int l = idx / 3, s = idx % 3;
        int l2 = (idx + 1) / 3, s2 = (idx + 1) % 3;
        float* outp = (idx == 5) ? (float*)d_out : bufs[bi];
        int S = Ss[s], B = Bs[s];
        const float* ksrc = (s == 1) ? x_pl : x_a;
        const float* rp   = (s == 0) ? rpe_t : (s == 1) ? rpe_pl : rpe_a;
        const int*   kn   = (s == 1) ? knn_pl : (s == 2) ? knn_a : (const int*)0;
        const unsigned char* mk = (s == 0) ? mk_t : (s == 1) ? mk_pl : mk_a;

        int P = 128 >> B;
        size_t smemB = (size_t)(2048 + P * 512 + S * 264) * sizeof(float);
        attn_core<<<NQ, 128, smemB>>>(gu, gw, ksrc, rp, kn, mk,
                                      gvb, grb, s + 1, S, B);

        int do_next = (idx < 5);
        const float* WqT2 = do_next ? WT(s2, 0, l2) : WT(0, 0, 0);
        const float* Wk2  = do_next ? W[s2][1] + l2 * H * H : W[0][1];
        const float* Wrk2 = do_next ? W[s2][3] + l2 * H * H : W[0][3];

        out_proj_uw<<<NQ / 4, 256>>>(cur, gvb, grb,
                                     WT(s, 1, l), WT(s, 2, l), WT(s, 3, l),
                                     outp, WqT2, Wk2, Wrk2, gu, gw, do_next);
        cur = outp;
        bi ^= 1;
    }
    #undef WT
}

// round 11
// speedup vs baseline: 1.5426x; 1.5426x over previous
#include <cuda_runtime.h>
#include <cstdint>

#define H  128
#define NH 8
#define NQ 2304

__device__ float g_WT[12 * H * H];
__device__ float g_u [NQ * 1024];
__device__ float g_w [NQ * 1024];
__device__ float g_vb[NQ * 1024];   // [q>>2][n*128+i][q&3]
__device__ float g_rb[NQ * 1024];
__device__ float g_buf0[NQ * H];
__device__ float g_buf1[NQ * H];

__global__ void transpose_k(const float* p0, const float* p1, const float* p2,
                            const float* p3, const float* p4, const float* p5)
{
    const float* ps[6] = {p0, p1, p2, p3, p4, p5};
    int slot = blockIdx.x >> 2;                  // 0..11
    int part = blockIdx.x & 3;
    const float* Wm = ps[slot >> 1] + (slot & 1) * H * H;
    float* O = g_WT + slot * H * H;
    int t = threadIdx.x;
    for (int c = part * 32; c < part * 32 + 32; ++c)
        O[c * H + t] = Wm[t * H + c];
}

__device__ __forceinline__ void cp16(uint32_t dst, const float* src) {
    asm volatile("cp.async.cg.shared.global [%0], [%1], 16;" :: "r"(dst), "l"(src));
}

// ---- u/w head projection from qh in smem (coalesced WkT[row*H+t] reads) ------
__device__ __forceinline__ void uw_heads(
    const float (*sqh)[128], int g, int t, int q0,
    const float* __restrict__ WkT, const float* __restrict__ WrkT,
    float* __restrict__ gu, float* __restrict__ gw)
{
    #pragma unroll 1
    for (int nn = 0; nn < 4; ++nn) {
        int n = 4 * g + nn;
        float wk[16], wr[16];
        #pragma unroll
        for (int d = 0; d < 16; ++d) {
            wk[d] = WkT [(n * 16 + d) * H + t];
            wr[d] = WrkT[(n * 16 + d) * H + t];
        }
        float uo[4], wo4[4];
        #pragma unroll
        for (int q = 0; q < 4; ++q) { uo[q] = 0.f; wo4[q] = 0.f; }
        #pragma unroll
        for (int d = 0; d < 16; ++d) {
            #pragma unroll
            for (int q = 0; q < 4; ++q) {
                float qv = sqh[q][n * 16 + d];
                uo[q]  += qv * wk[d];
                wo4[q] += qv * wr[d];
            }
        }
        #pragma unroll
        for (int q = 0; q < 4; ++q) {
            gu[(q0 + q) * 1024 + n * H + t] = uo[q];
            gw[(q0 + q) * 1024 + n * H + t] = wo4[q];
        }
    }
}

// ---------------- Kernel A (first stage only): qh = x@Wq; u/w ----------------
__global__ __launch_bounds__(256) void stage_uw(
    const float* __restrict__ xin,
    const float* __restrict__ Wq,
    const float* __restrict__ WkT, const float* __restrict__ WrkT,
    float* __restrict__ gu, float* __restrict__ gw)
{
    __shared__ float sx [4][128];
    __shared__ float sqh[4][128];
    const int tid = threadIdx.x;
    const int t = tid & 127, g = tid >> 7;
    const int q0 = blockIdx.x * 4;

    for (int e = tid; e < 512; e += 256)
        sx[e >> 7][e & 127] = xin[q0 * H + e];
    __syncthreads();

    {
        float a0 = 0.f, a1 = 0.f;
        const float* x0 = sx[2 * g];
        const float* x1 = sx[2 * g + 1];
        #pragma unroll 8
        for (int i = 0; i < H; ++i) {
            float wv = Wq[i * H + t];
            a0 += x0[i] * wv; a1 += x1[i] * wv;
        }
        sqh[2 * g    ][t] = a0;
        sqh[2 * g + 1][t] = a1;
    }
    __syncthreads();
    uw_heads(sqh, g, t, q0, WkT, WrkT, gu, gw);
}

// ---------------- Kernel B: weight-free attention core -----------------------
// B: log2 of s-slot width. P = 128>>B parts; part p covers i in [p<<B,(p+1)<<B).
__global__ __launch_bounds__(128) void attn_core(
    const float* __restrict__ gu, const float* __restrict__ gw,
    const float* __restrict__ ksrc, const float* __restrict__ rpesrc,
    const int* __restrict__ knn, const unsigned char* __restrict__ mask,
    float* __restrict__ gvb, float* __restrict__ grb,
    int stage, int S, int B)
{
    extern __shared__ float sm[];
    float* sm_u   = sm;                // 1024 [n*128+i]
    float* sm_w   = sm + 1024;         // 1024
    float* sm_scp = sm + 2048;         // P*512 partials; slot p=0 holds probs
    const int P = 128 >> B;
    float* sm_k   = sm_scp + P * 512;  // S*132
    float* sm_r   = sm_k + S * 132;

    __shared__ int kbase[64], rbase[64], mflag[64];

    const int q = blockIdx.x;
    const int t = threadIdx.x;

    if (t < S) {
        int kb, rb, mf;
        if (stage == 1) {
            kb = (q * S + t) * H; rb = kb;
            mf = mask[q * S + t];
        } else if (stage == 2) {
            int idx = knn[q * 32 + t];
            kb = (q * 128 + idx) * H; rb = kb;
            mf = mask[q * 128 + idx];
        } else {
            int g = q / 48, qn = q % 48;
            int idx = knn[(g * 48 + qn) * 16 + t];
            kb = ((g * 48 + idx) * 50 + 49) * H;
            rb = ((g * 48 + qn) * 48 + idx) * H;
            mf = mask[(g * 48 + qn) * 48 + idx];
        }
        kbase[t] = kb; rbase[t] = rb; mflag[t] = mf;
    }
    __syncthreads();

    {
        uint32_t su  = (uint32_t)__cvta_generic_to_shared(sm_u);
        uint32_t sw  = (uint32_t)__cvta_generic_to_shared(sm_w);
        for (int c = t; c < 256; c += 128) {
            cp16(su + c * 16, gu + q * 1024 + c * 4);
            cp16(sw + c * 16, gw + q * 1024 + c * 4);
        }
        uint32_t smk = (uint32_t)__cvta_generic_to_shared(sm_k);
        uint32_t smr = (uint32_t)__cvta_generic_to_shared(sm_r);
        for (int c = t; c < S * 32; c += 128) {
            int s = c >> 5, j = c & 31;
            cp16(smk + s * 528 + j * 16, ksrc   + kbase[s] + j * 4);
            cp16(smr + s * 528 + j * 16, rpesrc + rbase[s] + j * 4);
        }
        asm volatile("cp.async.commit_group;");
        asm volatile("cp.async.wait_group 0;");
    }
    __syncthreads();

    // scores: thread = (part p, key s).
    {
        int p = t >> B, s = t & ((1 << B) - 1);
        if (s < S) {
            int i0 = p << B;
            const int C = 1 << B;
            const float* kk = &sm_k[s * 132 + i0];
            const float* rr = &sm_r[s * 132 + i0];
            float acc[NH];
            #pragma unroll
            for (int n = 0; n < NH; ++n) acc[n] = 0.f;
            #pragma unroll 4
            for (int ii = 0; ii < C; ii += 4) {
                float4 k4 = *(const float4*)(kk + ii);
                float4 r4 = *(const float4*)(rr + ii);
                #pragma unroll
                for (int n = 0; n < NH; ++n) {
                    float4 u4 = *(const float4*)(sm_u + n * 128 + i0 + ii);
                    float4 w4 = *(const float4*)(sm_w + n * 128 + i0 + ii);
                    acc[n] += k4.x * u4.x + k4.y * u4.y + k4.z * u4.z + k4.w * u4.w
                            + r4.x * w4.x + r4.y * w4.y + r4.z * w4.z + r4.w * w4.w;
                }
            }
            #pragma unroll
            for (int n = 0; n < NH; ++n) sm_scp[p * 512 + s * NH + n] = acc[n];
        }
    }
    __syncthreads();

    // softmax: 128 threads, 16 lanes per head (xor 8,4,2,1 stays in-group).
    {
        int n = t >> 4, j = t & 15;
        float mx = -1e30f;
        for (int s = j; s < S; s += 16) {
            float v = 0.f;
            for (int p = 0; p < P; ++p) v += sm_scp[p * 512 + s * NH + n];
            v *= 0.25f;
            if (mflag[s]) v = -1e9f;
            sm_scp[s * NH + n] = v;
            mx = fmaxf(mx, v);
        }
        #pragma unroll
        for (int o = 8; o; o >>= 1) mx = fmaxf(mx, __shfl_xor_sync(0xffffffffu, mx, o));
        float sum = 0.f;
        for (int s = j; s < S; s += 16) {
            float pe = __expf(sm_scp[s * NH + n] - mx);
            sm_scp[s * NH + n] = pe; sum += pe;
        }
        #pragma unroll
        for (int o = 8; o; o >>= 1) sum += __shfl_xor_sync(0xffffffffu, sum, o);
        float inv = 1.f / sum;
        for (int s = j; s < S; s += 16) sm_scp[s * NH + n] *= inv;
    }
    __syncthreads();

    {
        float vb[NH], rb2[NH];
        #pragma unroll
        for (int n = 0; n < NH; ++n) { vb[n] = 0.f; rb2[n] = 0.f; }
        for (int s = 0; s < S; ++s) {
            float kv = sm_k[s * 132 + t];
            float rv = sm_r[s * 132 + t];
            float4 p0 = *(const float4*)&sm_scp[s * NH];
            float4 p1 = *(const float4*)&sm_scp[s * NH + 4];
            vb[0] += p0.x * kv;  rb2[0] += p0.x * rv;
            vb[1] += p0.y * kv;  rb2[1] += p0.y * rv;
            vb[2] += p0.z * kv;  rb2[2] += p0.z * rv;
            vb[3] += p0.w * kv;  rb2[3] += p0.w * rv;
            vb[4] += p1.x * kv;  rb2[4] += p1.x * rv;
            vb[5] += p1.y * kv;  rb2[5] += p1.y * rv;
            vb[6] += p1.z * kv;  rb2[6] += p1.z * rv;
            vb[7] += p1.w * kv;  rb2[7] += p1.w * rv;
        }
        int base = (q & ~3) * 1024 + (q & 3);
        #pragma unroll
        for (int n = 0; n < NH; ++n) {
            gvb[base + (n * 128 + t) * 4] = vb[n];
            grb[base + (n * 128 + t) * 4] = rb2[n];
        }
    }
}

// ---------------- Kernel C+A': out_proj fused with next-stage uw -------------
// block = 4 queries, 256 threads, grid 576.  (R9-proven version)
__global__ __launch_bounds__(256) void out_proj_uw(
    const float* __restrict__ xin,
    const float* __restrict__ gvb, const float* __restrict__ grb,
    const float* __restrict__ Wv, const float* __restrict__ Wrv,
    const float* __restrict__ Wo,
    float* __restrict__ xout,
    const float* __restrict__ Wq2,
    const float* __restrict__ WkT2, const float* __restrict__ WrkT2,
    float* __restrict__ gu, float* __restrict__ gw, int do_next)
{
    __shared__ __align__(16) float svb4[4096];   // [n*128+i][q]
    __shared__ __align__(16) float srb4[4096];
    __shared__ __align__(16) float sof4[512];    // [i][q]
    __shared__ float sxo[4][128];
    __shared__ float part[2][4][128];

    const int tid = threadIdx.x;
    const int t = tid & 127, g = tid >> 7;
    const int q0 = blockIdx.x * 4;
    const int n = t >> 4;
    const int i0 = g * 64;

    {
        uint32_t a = (uint32_t)__cvta_generic_to_shared(svb4);
        uint32_t b = (uint32_t)__cvta_generic_to_shared(srb4);
        for (int c = tid; c < 1024; c += 256) {
            cp16(a + c * 16, gvb + q0 * 1024 + c * 4);
            cp16(b + c * 16, grb + q0 * 1024 + c * 4);
        }
        asm volatile("cp.async.commit_group;");
        asm volatile("cp.async.wait_group 0;");
    }
    __syncthreads();

    // Phase 1: of[q][t] = vb[q][n]·Wv[:,t] + rb[q][n]·Wrv[:,t]  (i split by group)
    {
        float a0 = 0.f, a1 = 0.f, a2 = 0.f, a3 = 0.f;
        float b0 = 0.f, b1 = 0.f, b2 = 0.f, b3 = 0.f;
        #pragma unroll 4
        for (int ii = 0; ii < 64; ii += 2) {
            int i = i0 + ii;
            float wv0 = Wv [(i    ) * H + t], wr0 = Wrv[(i    ) * H + t];
            float wv1 = Wv [(i + 1) * H + t], wr1 = Wrv[(i + 1) * H + t];
            float4 v0 = *(const float4*)&svb4[(n * 128 + i    ) * 4];
            float4 r0 = *(const float4*)&srb4[(n * 128 + i    ) * 4];
            float4 v1 = *(const float4*)&svb4[(n * 128 + i + 1) * 4];
            float4 r1 = *(const float4*)&srb4[(n * 128 + i + 1) * 4];
            a0 += v0.x * wv0 + r0.x * wr0;  b0 += v1.x * wv1 + r1.x * wr1;
            a1 += v0.y * wv0 + r0.y * wr0;  b1 += v1.y * wv1 + r1.y * wr1;
            a2 += v0.z * wv0 + r0.z * wr0;  b2 += v1.z * wv1 + r1.z * wr1;
            a3 += v0.w * wv0 + r0.w * wr0;  b3 += v1.w * wv1 + r1.w * wr1;
        }
        part[g][0][t] = a0 + b0; part[g][1][t] = a1 + b1;
        part[g][2][t] = a2 + b2; part[g][3][t] = a3 + b3;
    }
    __syncthreads();
    if (g == 0) {
        float4 o;
        o.x = part[0][0][t] + part[1][0][t];
        o.y = part[0][1][t] + part[1][1][t];
        o.z = part[0][2][t] + part[1][2][t];
        o.w = part[0][3][t] + part[1][3][t];
        *(float4*)&sof4[t * 4] = o;
    }
    __syncthreads();

    // Phase 2: x_out = x + of @ Wo  (i split by group)
    {
        float a0 = 0.f, a1 = 0.f, a2 = 0.f, a3 = 0.f;
        float b0 = 0.f, b1 = 0.f, b2 = 0.f, b3 = 0.f;
        #pragma unroll 4
        for (int ii = 0; ii < 64; ii += 2) {
            int i = i0 + ii;
            float wo0 = Wo[(i    ) * H + t];
            float wo1 = Wo[(i + 1) * H + t];
            float4 f0 = *(const float4*)&sof4[(i    ) * 4];
            float4 f1 = *(const float4*)&sof4[(i + 1) * 4];
            a0 += f0.x * wo0;  b0 += f1.x * wo1;
            a1 += f0.y * wo0;  b1 += f1.y * wo1;
            a2 += f0.z * wo0;  b2 += f1.z * wo1;
            a3 += f0.w * wo0;  b3 += f1.w * wo1;
        }
        part[g][0][t] = a0 + b0; part[g][1][t] = a1 + b1;
        part[g][2][t] = a2 + b2; part[g][3][t] = a3 + b3;
    }
    __syncthreads();
    if (g == 0) {
        #pragma unroll
        for (int q = 0; q < 4; ++q) {
            float v = xin[(q0 + q) * H + t] + part[0][q][t] + part[1][q][t];
            sxo[q][t] = v;
            xout[(q0 + q) * H + t] = v;
        }
    }
    __syncthreads();

    if (!do_next) return;

    // Phase 3: next-stage qh = x_out @ Wq2
    {
        float a0 = 0.f, a1 = 0.f;
        const float* x0 = sxo[2 * g];
        const float* x1 = sxo[2 * g + 1];
        #pragma unroll 8
        for (int i = 0; i < H; ++i) {
            float wv = Wq2[i * H + t];
            a0 += x0[i] * wv; a1 += x1[i] * wv;
        }
        part[0][2 * g    ][t] = a0;
        part[0][2 * g + 1][t] = a1;
    }
    __syncthreads();

    // Phase 4: next-stage u/w.
    uw_heads((const float (*)[128])part[0], g, t, q0, WkT2, WrkT2, gu, gw);
}

extern "C" void kernel_launch(void* const* d_in, const int* in_sizes, int n_in,
                              void* d_out, int out_size)
{
    bool sig = (in_sizes[6] == 32768);

    const float* x_m    = (const float*)d_in[0];
    const float* x_a    = (const float*)d_in[1];
    const float* x_pl   = (const float*)d_in[2];
    const float* rpe_t  = (const float*)d_in[3];
    const float* rpe_pl = (const float*)d_in[4];
    const float* rpe_a  = (const float*)d_in[5];

    const float* W[3][6];
    int wb = sig ? 6 : 11;
    for (int s = 0; s < 3; ++s)
        for (int j = 0; j < 6; ++j)
            W[s][j] = (const float*)d_in[wb + s * 6 + j];

    int kb = sig ? 24 : 6;
    const int* knn_pl = (const int*)d_in[kb + 0];
    const int* knn_a  = (const int*)d_in[kb + 1];
    const unsigned char* mk_t  = (const unsigned char*)d_in[kb + 2];
    const unsigned char* mk_pl = (const unsigned char*)d_in[kb + 3];
    const unsigned char* mk_a  = (const unsigned char*)d_in[kb + 4];

    cudaFuncSetAttribute(attn_core, cudaFuncAttributeMaxDynamicSharedMemorySize, 65088);

    float *buf0, *buf1, *wt, *gu, *gw, *gvb, *grb;
    cudaGetSymbolAddress((void**)&buf0, g_buf0);
    cudaGetSymbolAddress((void**)&buf1, g_buf1);
    cudaGetSymbolAddress((void**)&wt,   g_WT);
    cudaGetSymbolAddress((void**)&gu,   g_u);
    cudaGetSymbolAddress((void**)&gw,   g_w);
    cudaGetSymbolAddress((void**)&gvb,  g_vb);
    cudaGetSymbolAddress((void**)&grb,  g_rb);

    transpose_k<<<48, 128>>>(W[0][1], W[0][3], W[1][1], W[1][3], W[2][1], W[2][3]);

    const int Ss[3] = {50, 32, 16};
    const int Bs[3] = {6, 5, 4};
    const float* cur = x_m;
    float* bufs[2] = {buf0, buf1};
    int bi = 0;

    // First-stage u/w.
    stage_uw<<<NQ / 4, 256>>>(x_m, W[0][0],
                              wt + ((0 * 2 + 0) * 2 + 0) * H * H,
                              wt + ((0 * 2 + 1) * 2 + 0) * H * H, gu, gw);

    for (int idx = 0; idx < 6; ++idx) {
        int l = idx / 3, s = idx % 3;
        int l2 = (idx + 1) / 3, s2 = (idx + 1) % 3;
        float* outp = (idx == 5) ? (float*)d_out : bufs[bi];
        int S = Ss[s], B = Bs[s];
        const float* ksrc = (s == 1) ? x_pl : x_a;
        const float* rp   = (s == 0) ? rpe_t : (s == 1) ? rpe_pl : rpe_a;
        const int*   kn   = (s == 1) ? knn_pl : (s == 2) ? knn_a : (const int*)0;
        const unsigned char* mk = (s == 0) ? mk_t : (s == 1) ? mk_pl : mk_a;

        const float* Wv  = W[s][2] + l * H * H;
        const float* Wrv = W[s][4] + l * H * H;
        const float* Wo  = W[s][5] + l * H * H;

        int P = 128 >> B;
        size_t smemB = (size_t)(2048 + P * 512 + S * 264) * sizeof(float);
        attn_core<<<NQ, 128, smemB>>>(gu, gw, ksrc, rp, kn, mk,
                                      gvb, grb, s + 1, S, B);

        int do_next = (idx < 5);
        const float* Wq2   = do_next ? W[s2][0] + l2 * H * H : Wv;
        const float* WkT2  = do_next ? wt + ((s2 * 2 + 0) * 2 + l2) * H * H : Wv;
        const float* WrkT2 = do_next ? wt + ((s2 * 2 + 1) * 2 + l2) * H * H : Wv;

        out_proj_uw<<<NQ / 4, 256>>>(cur, gvb, grb, Wv, Wrv, Wo, outp,
                                     Wq2, WkT2, WrkT2, gu, gw, do_next);
        cur = outp;
        bi ^= 1;
    }
}